// round 1
// baseline (speedup 1.0000x reference)
#include <cuda_runtime.h>

// MagnetohydrodynamicsPhysics: lorentz = curl(B) x B * 50^2  +  0.1 * MLP([v,B])
// Scalar fp32 baseline: 1 thread = 1 voxel, weights in smem (broadcast reads),
// activations in smem transposed [feat][tid], fp32 end-to-end.

#define SP 262144           // 64*64*64 spatial size per (batch, channel)
#define NVOX 524288         // 2 * 64^3
#define TB 128              // threads per block

// smem float layout (word offsets)
#define O_W1   0            // 6*128   = 768
#define O_B1   768          // 128
#define O_W2   896          // 128*128 = 16384
#define O_B2   17280        // 128
#define O_B3   17408        // 64
#define O_W4   17472        // 64*3    = 192
#define O_B4   17664        // 3 (+1 pad)
#define O_X1   17668        // 128*TB fp32
#define O_X2   (O_X1 + 128*TB)
#define SMEM_WORDS (O_X2 + 128*TB)   // 50436 words = 201744 bytes

__device__ __forceinline__ float gelu_exact(float x) {
    return 0.5f * x * (1.0f + erff(x * 0.70710678118654752440f));
}

__global__ void __launch_bounds__(TB, 1)
mhd_kernel(const float* __restrict__ flow, const float* __restrict__ Bf,
           const float* __restrict__ W1, const float* __restrict__ b1,
           const float* __restrict__ W2, const float* __restrict__ b2,
           const float* __restrict__ W3, const float* __restrict__ b3,
           const float* __restrict__ W4, const float* __restrict__ b4,
           float* __restrict__ out)
{
    extern __shared__ float sm[];
    const int tid = threadIdx.x;

    // ---- stage weights into smem (W3 stays in L2: uniform-address LDG) ----
    for (int i = tid; i < 768;   i += TB) sm[O_W1 + i] = W1[i];
    for (int i = tid; i < 128;   i += TB) sm[O_B1 + i] = b1[i];
    for (int i = tid; i < 16384; i += TB) sm[O_W2 + i] = W2[i];
    for (int i = tid; i < 128;   i += TB) sm[O_B2 + i] = b2[i];
    for (int i = tid; i < 64;    i += TB) sm[O_B3 + i] = b3[i];
    for (int i = tid; i < 192;   i += TB) sm[O_W4 + i] = W4[i];
    if (tid < 3) sm[O_B4 + tid] = b4[tid];
    __syncthreads();

    float* x1s = sm + O_X1;   // [128][TB] fp32
    float* x2s = sm + O_X2;   // [128][TB] fp32

    // ---- voxel decode ----
    const int v = blockIdx.x * TB + tid;
    const int b = v >> 18;
    const int s = v & (SP - 1);
    const int h = s >> 12, w = (s >> 6) & 63, d = s & 63;

    const float* Fb = flow + b * 3 * SP;
    const float* Bb = Bf   + b * 3 * SP;
    const float* Bx = Bb;
    const float* By = Bb + SP;
    const float* Bz = Bb + 2 * SP;

    const int H  = h << 12,             Wo = w << 6;
    const int hp = ((h + 1) & 63) << 12, hm = ((h - 1) & 63) << 12;
    const int wp = ((w + 1) & 63) << 6,  wm = ((w - 1) & 63) << 6;
    const int dp = (d + 1) & 63,         dm = (d - 1) & 63;

    const float bx = Bx[H + Wo + d], by = By[H + Wo + d], bz = Bz[H + Wo + d];

    // periodic central differences: grad[i] = 0.5*(f[i+1]-f[i-1])
    const float Jx = 0.5f * ((Bz[H + wp + d] - Bz[H + wm + d]) - (By[H + Wo + dp] - By[H + Wo + dm]));
    const float Jy = 0.5f * ((Bx[H + Wo + dp] - Bx[H + Wo + dm]) - (Bz[hp + Wo + d] - Bz[hm + Wo + d]));
    const float Jz = 0.5f * ((By[hp + Wo + d] - By[hm + Wo + d]) - (Bx[H + wp + d] - Bx[H + wm + d]));

    const float HSQ = 2500.0f;  // HARTMANN^2
    const float lx = (Jy * bz - Jz * by) * HSQ;
    const float ly = (Jz * bx - Jx * bz) * HSQ;
    const float lz = (Jx * by - Jy * bx) * HSQ;

    float cf[6];
    cf[0] = Fb[s]; cf[1] = Fb[SP + s]; cf[2] = Fb[2 * SP + s];
    cf[3] = bx;    cf[4] = by;         cf[5] = bz;

    // ---- layer 1: 6 -> 128 ----
    #pragma unroll 1
    for (int j = 0; j < 128; j += 8) {
        float acc[8];
        #pragma unroll
        for (int k = 0; k < 8; k++) acc[k] = sm[O_B1 + j + k];
        #pragma unroll
        for (int i = 0; i < 6; i++) {
            const float xi = cf[i];
            const float4* wr = (const float4*)(sm + O_W1 + i * 128 + j);
            const float4 wa = wr[0], wb = wr[1];
            acc[0] += xi * wa.x; acc[1] += xi * wa.y; acc[2] += xi * wa.z; acc[3] += xi * wa.w;
            acc[4] += xi * wb.x; acc[5] += xi * wb.y; acc[6] += xi * wb.z; acc[7] += xi * wb.w;
        }
        #pragma unroll
        for (int k = 0; k < 8; k++) x1s[(j + k) * TB + tid] = gelu_exact(acc[k]);
    }

    // ---- layer 2: 128 -> 128 (dominant cost) ----
    #pragma unroll 1
    for (int j = 0; j < 128; j += 8) {
        float acc[8];
        #pragma unroll
        for (int k = 0; k < 8; k++) acc[k] = sm[O_B2 + j + k];
        #pragma unroll 4
        for (int i = 0; i < 128; i++) {
            const float xi = x1s[i * TB + tid];
            const float4* wr = (const float4*)(sm + O_W2 + i * 128 + j);
            const float4 wa = wr[0], wb = wr[1];
            acc[0] += xi * wa.x; acc[1] += xi * wa.y; acc[2] += xi * wa.z; acc[3] += xi * wa.w;
            acc[4] += xi * wb.x; acc[5] += xi * wb.y; acc[6] += xi * wb.z; acc[7] += xi * wb.w;
        }
        #pragma unroll
        for (int k = 0; k < 8; k++) x2s[(j + k) * TB + tid] = gelu_exact(acc[k]);
    }

    // ---- layer 3: 128 -> 64 (W3 from global, uniform address -> 1 req/warp) ----
    #pragma unroll 1
    for (int j = 0; j < 64; j += 8) {
        float acc[8];
        #pragma unroll
        for (int k = 0; k < 8; k++) acc[k] = sm[O_B3 + j + k];
        #pragma unroll 4
        for (int i = 0; i < 128; i++) {
            const float xi = x2s[i * TB + tid];
            const float4* wr = (const float4*)(W3 + i * 64 + j);
            const float4 wa = __ldg(wr), wb = __ldg(wr + 1);
            acc[0] += xi * wa.x; acc[1] += xi * wa.y; acc[2] += xi * wa.z; acc[3] += xi * wa.w;
            acc[4] += xi * wb.x; acc[5] += xi * wb.y; acc[6] += xi * wb.z; acc[7] += xi * wb.w;
        }
        // x1s is dead now: reuse rows [0,64) for x3
        #pragma unroll
        for (int k = 0; k < 8; k++) x1s[(j + k) * TB + tid] = gelu_exact(acc[k]);
    }

    // ---- layer 4: 64 -> 3 ----
    float e0 = sm[O_B4 + 0], e1 = sm[O_B4 + 1], e2 = sm[O_B4 + 2];
    #pragma unroll 4
    for (int i = 0; i < 64; i++) {
        const float xi = x1s[i * TB + tid];
        e0 += xi * sm[O_W4 + i * 3 + 0];
        e1 += xi * sm[O_W4 + i * 3 + 1];
        e2 += xi * sm[O_W4 + i * 3 + 2];
    }

    float* ob = out + b * 3 * SP;
    ob[s]          = lx + 0.1f * e0;
    ob[SP + s]     = ly + 0.1f * e1;
    ob[2 * SP + s] = lz + 0.1f * e2;
}

extern "C" void kernel_launch(void* const* d_in, const int* in_sizes, int n_in,
                              void* d_out, int out_size)
{
    (void)in_sizes; (void)n_in; (void)out_size;
    const float* flow = (const float*)d_in[0];
    const float* Bf   = (const float*)d_in[1];
    const float* W1   = (const float*)d_in[2];
    const float* b1   = (const float*)d_in[3];
    const float* W2   = (const float*)d_in[4];
    const float* b2   = (const float*)d_in[5];
    const float* W3   = (const float*)d_in[6];
    const float* b3   = (const float*)d_in[7];
    const float* W4   = (const float*)d_in[8];
    const float* b4   = (const float*)d_in[9];
    float* out = (float*)d_out;

    const size_t smem_bytes = SMEM_WORDS * sizeof(float);  // 201744
    cudaFuncSetAttribute(mhd_kernel, cudaFuncAttributeMaxDynamicSharedMemorySize,
                         (int)smem_bytes);

    mhd_kernel<<<NVOX / TB, TB, smem_bytes>>>(flow, Bf, W1, b1, W2, b2, W3, b3,
                                              W4, b4, out);
}

// round 3
// speedup vs baseline: 1.0017x; 1.0017x over previous
#include <cuda_runtime.h>

// MagnetohydrodynamicsPhysics: lorentz = curl(B) x B * 50^2  +  0.1 * MLP([v,B])
// Scalar fp32 baseline: 1 thread = 1 voxel, weights in smem (broadcast reads),
// activations in smem transposed [feat][tid], fp32 end-to-end.

#define SP 262144           // 64*64*64 spatial size per (batch, channel)
#define NVOX 524288         // 2 * 64^3
#define TB 128              // threads per block

// smem float layout (word offsets)
#define O_W1   0            // 6*128   = 768
#define O_B1   768          // 128
#define O_W2   896          // 128*128 = 16384
#define O_B2   17280        // 128
#define O_B3   17408        // 64
#define O_W4   17472        // 64*3    = 192
#define O_B4   17664        // 3 (+1 pad)
#define O_X1   17668        // 128*TB fp32
#define O_X2   (O_X1 + 128*TB)
#define SMEM_WORDS (O_X2 + 128*TB)   // 50436 words = 201744 bytes

__device__ __forceinline__ float gelu_exact(float x) {
    return 0.5f * x * (1.0f + erff(x * 0.70710678118654752440f));
}

__global__ void __launch_bounds__(TB, 1)
mhd_kernel(const float* __restrict__ flow, const float* __restrict__ Bf,
           const float* __restrict__ W1, const float* __restrict__ b1,
           const float* __restrict__ W2, const float* __restrict__ b2,
           const float* __restrict__ W3, const float* __restrict__ b3,
           const float* __restrict__ W4, const float* __restrict__ b4,
           float* __restrict__ out)
{
    extern __shared__ float sm[];
    const int tid = threadIdx.x;

    // ---- stage weights into smem (W3 stays in L2: uniform-address LDG) ----
    for (int i = tid; i < 768;   i += TB) sm[O_W1 + i] = W1[i];
    for (int i = tid; i < 128;   i += TB) sm[O_B1 + i] = b1[i];
    for (int i = tid; i < 16384; i += TB) sm[O_W2 + i] = W2[i];
    for (int i = tid; i < 128;   i += TB) sm[O_B2 + i] = b2[i];
    for (int i = tid; i < 64;    i += TB) sm[O_B3 + i] = b3[i];
    for (int i = tid; i < 192;   i += TB) sm[O_W4 + i] = W4[i];
    if (tid < 3) sm[O_B4 + tid] = b4[tid];
    __syncthreads();

    float* x1s = sm + O_X1;   // [128][TB] fp32
    float* x2s = sm + O_X2;   // [128][TB] fp32

    // ---- voxel decode ----
    const int v = blockIdx.x * TB + tid;
    const int b = v >> 18;
    const int s = v & (SP - 1);
    const int h = s >> 12, w = (s >> 6) & 63, d = s & 63;

    const float* Fb = flow + b * 3 * SP;
    const float* Bb = Bf   + b * 3 * SP;
    const float* Bx = Bb;
    const float* By = Bb + SP;
    const float* Bz = Bb + 2 * SP;

    const int H  = h << 12,             Wo = w << 6;
    const int hp = ((h + 1) & 63) << 12, hm = ((h - 1) & 63) << 12;
    const int wp = ((w + 1) & 63) << 6,  wm = ((w - 1) & 63) << 6;
    const int dp = (d + 1) & 63,         dm = (d - 1) & 63;

    const float bx = Bx[H + Wo + d], by = By[H + Wo + d], bz = Bz[H + Wo + d];

    // periodic central differences: grad[i] = 0.5*(f[i+1]-f[i-1])
    const float Jx = 0.5f * ((Bz[H + wp + d] - Bz[H + wm + d]) - (By[H + Wo + dp] - By[H + Wo + dm]));
    const float Jy = 0.5f * ((Bx[H + Wo + dp] - Bx[H + Wo + dm]) - (Bz[hp + Wo + d] - Bz[hm + Wo + d]));
    const float Jz = 0.5f * ((By[hp + Wo + d] - By[hm + Wo + d]) - (Bx[H + wp + d] - Bx[H + wm + d]));

    const float HSQ = 2500.0f;  // HARTMANN^2
    const float lx = (Jy * bz - Jz * by) * HSQ;
    const float ly = (Jz * bx - Jx * bz) * HSQ;
    const float lz = (Jx * by - Jy * bx) * HSQ;

    float cf[6];
    cf[0] = Fb[s]; cf[1] = Fb[SP + s]; cf[2] = Fb[2 * SP + s];
    cf[3] = bx;    cf[4] = by;         cf[5] = bz;

    // ---- layer 1: 6 -> 128 ----
    #pragma unroll 1
    for (int j = 0; j < 128; j += 8) {
        float acc[8];
        #pragma unroll
        for (int k = 0; k < 8; k++) acc[k] = sm[O_B1 + j + k];
        #pragma unroll
        for (int i = 0; i < 6; i++) {
            const float xi = cf[i];
            const float4* wr = (const float4*)(sm + O_W1 + i * 128 + j);
            const float4 wa = wr[0], wb = wr[1];
            acc[0] += xi * wa.x; acc[1] += xi * wa.y; acc[2] += xi * wa.z; acc[3] += xi * wa.w;
            acc[4] += xi * wb.x; acc[5] += xi * wb.y; acc[6] += xi * wb.z; acc[7] += xi * wb.w;
        }
        #pragma unroll
        for (int k = 0; k < 8; k++) x1s[(j + k) * TB + tid] = gelu_exact(acc[k]);
    }

    // ---- layer 2: 128 -> 128 (dominant cost) ----
    #pragma unroll 1
    for (int j = 0; j < 128; j += 8) {
        float acc[8];
        #pragma unroll
        for (int k = 0; k < 8; k++) acc[k] = sm[O_B2 + j + k];
        #pragma unroll 4
        for (int i = 0; i < 128; i++) {
            const float xi = x1s[i * TB + tid];
            const float4* wr = (const float4*)(sm + O_W2 + i * 128 + j);
            const float4 wa = wr[0], wb = wr[1];
            acc[0] += xi * wa.x; acc[1] += xi * wa.y; acc[2] += xi * wa.z; acc[3] += xi * wa.w;
            acc[4] += xi * wb.x; acc[5] += xi * wb.y; acc[6] += xi * wb.z; acc[7] += xi * wb.w;
        }
        #pragma unroll
        for (int k = 0; k < 8; k++) x2s[(j + k) * TB + tid] = gelu_exact(acc[k]);
    }

    // ---- layer 3: 128 -> 64 (W3 from global, uniform address -> 1 req/warp) ----
    #pragma unroll 1
    for (int j = 0; j < 64; j += 8) {
        float acc[8];
        #pragma unroll
        for (int k = 0; k < 8; k++) acc[k] = sm[O_B3 + j + k];
        #pragma unroll 4
        for (int i = 0; i < 128; i++) {
            const float xi = x2s[i * TB + tid];
            const float4* wr = (const float4*)(W3 + i * 64 + j);
            const float4 wa = __ldg(wr), wb = __ldg(wr + 1);
            acc[0] += xi * wa.x; acc[1] += xi * wa.y; acc[2] += xi * wa.z; acc[3] += xi * wa.w;
            acc[4] += xi * wb.x; acc[5] += xi * wb.y; acc[6] += xi * wb.z; acc[7] += xi * wb.w;
        }
        // x1s is dead now: reuse rows [0,64) for x3
        #pragma unroll
        for (int k = 0; k < 8; k++) x1s[(j + k) * TB + tid] = gelu_exact(acc[k]);
    }

    // ---- layer 4: 64 -> 3 ----
    float e0 = sm[O_B4 + 0], e1 = sm[O_B4 + 1], e2 = sm[O_B4 + 2];
    #pragma unroll 4
    for (int i = 0; i < 64; i++) {
        const float xi = x1s[i * TB + tid];
        e0 += xi * sm[O_W4 + i * 3 + 0];
        e1 += xi * sm[O_W4 + i * 3 + 1];
        e2 += xi * sm[O_W4 + i * 3 + 2];
    }

    float* ob = out + b * 3 * SP;
    ob[s]          = lx + 0.1f * e0;
    ob[SP + s]     = ly + 0.1f * e1;
    ob[2 * SP + s] = lz + 0.1f * e2;
}

extern "C" void kernel_launch(void* const* d_in, const int* in_sizes, int n_in,
                              void* d_out, int out_size)
{
    (void)in_sizes; (void)n_in; (void)out_size;
    const float* flow = (const float*)d_in[0];
    const float* Bf   = (const float*)d_in[1];
    const float* W1   = (const float*)d_in[2];
    const float* b1   = (const float*)d_in[3];
    const float* W2   = (const float*)d_in[4];
    const float* b2   = (const float*)d_in[5];
    const float* W3   = (const float*)d_in[6];
    const float* b3   = (const float*)d_in[7];
    const float* W4   = (const float*)d_in[8];
    const float* b4   = (const float*)d_in[9];
    float* out = (float*)d_out;

    const size_t smem_bytes = SMEM_WORDS * sizeof(float);  // 201744
    cudaFuncSetAttribute(mhd_kernel, cudaFuncAttributeMaxDynamicSharedMemorySize,
                         (int)smem_bytes);

    mhd_kernel<<<NVOX / TB, TB, smem_bytes>>>(flow, Bf, W1, b1, W2, b2, W3, b3,
                                              W4, b4, out);
}

// round 7
// speedup vs baseline: 18.5387x; 18.5072x over previous
#include <cuda_runtime.h>
#include <cuda_fp16.h>
#include <cstdint>

// lorentz (fp32 exact) + 0.1 * MLP via mma.sync m16n8k16 (f16 in, f32 accum).
// Compiles for plain sm_103 (no tcgen05 / no 'a'-target features).

#define SP    262144
#define TB    256
#define GRID  2048
#define TILES 2          // 2048*2*128 = 524288 voxels

// smem byte offsets
#define O_X    0         // [128 rows][136 halfs] = 34816 B (272 B stride)
#define O_W2T  34816     // 4096 frag entries * 8B = 32768
#define O_W3T  67584     // 2048 * 8 = 16384
#define O_W1T  83968     // 512  * 8 = 4096
#define O_B1   88064     // 128 f32
#define O_B2   88576
#define O_B3   89088     // 64 f32
#define O_W4   89344     // 192 f32
#define O_B4   90112     // 3 f32
#define SMEM_BYTES 90128
#define XSTRIDE 272      // bytes per activation row

#define LDSM4(a, addr) asm volatile( \
    "ldmatrix.sync.aligned.m8n8.x4.shared.b16 {%0,%1,%2,%3}, [%4];" \
    : "=r"((a)[0]), "=r"((a)[1]), "=r"((a)[2]), "=r"((a)[3]) : "r"(addr))

#define MMA(c, a, b) asm volatile( \
    "mma.sync.aligned.m16n8k16.row.col.f32.f16.f16.f32 " \
    "{%0,%1,%2,%3}, {%4,%5,%6,%7}, {%8,%9}, {%0,%1,%2,%3};" \
    : "+f"((c)[0]), "+f"((c)[1]), "+f"((c)[2]), "+f"((c)[3]) \
    : "r"((a)[0]), "r"((a)[1]), "r"((a)[2]), "r"((a)[3]), "r"((b).x), "r"((b).y))

__device__ __forceinline__ uint32_t smem_u32(const void* p) {
    uint32_t a;
    asm("{ .reg .u64 t; cvta.to.shared.u64 t, %1; cvt.u32.u64 %0, t; }" : "=r"(a) : "l"(p));
    return a;
}
__device__ __forceinline__ uint2 lds_u2(uint32_t addr) {
    uint2 v;
    asm volatile("ld.shared.v2.b32 {%0,%1}, [%2];" : "=r"(v.x), "=r"(v.y) : "r"(addr));
    return v;
}
__device__ __forceinline__ uint32_t packh(float a, float b) {
    __half2 h = __floats2half2_rn(a, b);
    return *(uint32_t*)&h;
}
__device__ __forceinline__ uint32_t gelu_pack(float a, float b) {
    // gelu (tanh form) on a packed pair, f16x2 arithmetic
    __half2 x = __floats2half2_rn(a, b);
    const __half2 c0 = __float2half2_rn(0.7978845608f);
    const __half2 c1 = __float2half2_rn(0.03567740814f);
    __half2 u = __hmul2(x, x);
    __half2 z = __hmul2(x, __hfma2(u, c1, c0));
    uint32_t zi = *(uint32_t*)&z, ti;
    asm("tanh.approx.f16x2 %0, %1;" : "=r"(ti) : "r"(zi));
    __half2 t = *(__half2*)&ti;
    __half2 hh = __hmul2(x, __float2half2_rn(0.5f));
    __half2 g = __hfma2(hh, t, hh);
    return *(uint32_t*)&g;
}

// epilogue: C frags -> +bias -> gelu -> f16 into X
template <int NT>
__device__ __forceinline__ void epilogue(float c[4][4][4], int nbase, const float* bias,
                                         char* smc, int wm, int lane) {
    const int rsub = lane >> 2;
    const int ncol = (lane & 3) * 2;
    #pragma unroll
    for (int m = 0; m < 4; m++) {
        const int row0 = (wm * 4 + m) * 16 + rsub;
        #pragma unroll
        for (int t = 0; t < NT; t++) {
            const int n = nbase + t * 8 + ncol;
            const float b0 = bias[n], b1 = bias[n + 1];
            uint32_t g01 = gelu_pack(c[m][t][0] + b0, c[m][t][1] + b1);
            uint32_t g23 = gelu_pack(c[m][t][2] + b0, c[m][t][3] + b1);
            *(uint32_t*)(smc + O_X + row0 * XSTRIDE + n * 2) = g01;
            *(uint32_t*)(smc + O_X + (row0 + 8) * XSTRIDE + n * 2) = g23;
        }
    }
}

__global__ void __launch_bounds__(TB, 2)
mhd_mma(const float* __restrict__ flow, const float* __restrict__ Bf,
        const float* __restrict__ W1, const float* __restrict__ b1,
        const float* __restrict__ W2, const float* __restrict__ b2,
        const float* __restrict__ W3, const float* __restrict__ b3,
        const float* __restrict__ W4, const float* __restrict__ b4,
        float* __restrict__ out)
{
    extern __shared__ char smc[];
    const int tid  = threadIdx.x;
    const int wid  = tid >> 5;
    const int lane = tid & 31;
    const int wm   = wid >> 2;      // 0..1 : M half
    const int wn   = wid & 3;       // 0..3 : N quarter
    const uint32_t smb = smem_u32(smc);

    // ---------------- stage weight fragment tables ----------------
    // W2 frags: entry e = ((wn*8+s)*4+t)*32+lane ; n = wn*32+t*8+lane/4 ; k0 = s*16+(lane%4)*2
    for (int e = tid; e < 4096; e += TB) {
        int l = e & 31, t = (e >> 5) & 3, s = (e >> 7) & 7, w = e >> 10;
        int n = w * 32 + t * 8 + (l >> 2);
        int k0 = s * 16 + (l & 3) * 2;
        uint2 v;
        v.x = packh(W2[k0 * 128 + n], W2[(k0 + 1) * 128 + n]);
        v.y = packh(W2[(k0 + 8) * 128 + n], W2[(k0 + 9) * 128 + n]);
        *(uint2*)(smc + O_W2T + e * 8) = v;
    }
    // W3 frags: entry e = ((wn*8+s)*2+t)*32+lane ; n = wn*16+t*8+lane/4
    for (int e = tid; e < 2048; e += TB) {
        int l = e & 31, t = (e >> 5) & 1, s = (e >> 6) & 7, w = e >> 9;
        int n = w * 16 + t * 8 + (l >> 2);
        int k0 = s * 16 + (l & 3) * 2;
        uint2 v;
        v.x = packh(W3[k0 * 64 + n], W3[(k0 + 1) * 64 + n]);
        v.y = packh(W3[(k0 + 8) * 64 + n], W3[(k0 + 9) * 64 + n]);
        *(uint2*)(smc + O_W3T + e * 8) = v;
    }
    // W1 frags: entry e = (wn*4+t)*32+lane ; k0 = (lane%4)*2 ; rows k>=6 zero
    for (int e = tid; e < 512; e += TB) {
        int l = e & 31, t = (e >> 5) & 3, w = e >> 7;
        int n = w * 32 + t * 8 + (l >> 2);
        int k0 = (l & 3) * 2;
        float f0 = (k0 < 6) ? W1[k0 * 128 + n] : 0.f;
        float f1 = (k0 + 1 < 6) ? W1[(k0 + 1) * 128 + n] : 0.f;
        uint2 v;
        v.x = packh(f0, f1);
        v.y = 0u;                      // k0+8, k0+9 >= 8 -> zero
        *(uint2*)(smc + O_W1T + e * 8) = v;
    }
    for (int i = tid; i < 128; i += TB) ((float*)(smc + O_B1))[i] = b1[i];
    for (int i = tid; i < 128; i += TB) ((float*)(smc + O_B2))[i] = b2[i];
    for (int i = tid; i < 64;  i += TB) ((float*)(smc + O_B3))[i] = b3[i];
    for (int i = tid; i < 192; i += TB) ((float*)(smc + O_W4))[i] = W4[i];
    if (tid < 3) ((float*)(smc + O_B4))[tid] = b4[tid];

    // ldmatrix lane base address into X
    const uint32_t abase = smb + O_X + (uint32_t)(lane & 15) * XSTRIDE + ((lane >> 4) << 4);
    const float* bias1 = (const float*)(smc + O_B1);
    const float* bias2 = (const float*)(smc + O_B2);
    const float* bias3 = (const float*)(smc + O_B3);

    for (int it = 0; it < TILES; it++) {
        const int tile = it * GRID + blockIdx.x;
        __syncthreads();   // staging done / X free from previous tile's L4 readers

        // ---------------- P0: features + lorentz (tid < 128) ----------------
        float lx = 0.f, ly = 0.f, lz = 0.f;
        const int r = tid;
        const int v = tile * 128 + r;
        const int b = v >> 18;
        const int s = v & (SP - 1);
        if (tid < 128) {
            const int h = s >> 12, w = (s >> 6) & 63, d = s & 63;
            const float* Fb = flow + b * 3 * SP;
            const float* Bx = Bf + b * 3 * SP;
            const float* By = Bx + SP;
            const float* Bz = Bx + 2 * SP;
            const int H = h << 12, Wo = w << 6;
            const int hp = ((h + 1) & 63) << 12, hm = ((h - 1) & 63) << 12;
            const int wp = ((w + 1) & 63) << 6,  wm2 = ((w - 1) & 63) << 6;
            const int dp = (d + 1) & 63, dm = (d - 1) & 63;
            const float bx = Bx[H + Wo + d], by = By[H + Wo + d], bz = Bz[H + Wo + d];
            const float Jx = 0.5f * ((Bz[H + wp + d] - Bz[H + wm2 + d]) - (By[H + Wo + dp] - By[H + Wo + dm]));
            const float Jy = 0.5f * ((Bx[H + Wo + dp] - Bx[H + Wo + dm]) - (Bz[hp + Wo + d] - Bz[hm + Wo + d]));
            const float Jz = 0.5f * ((By[hp + Wo + d] - By[hm + Wo + d]) - (Bx[H + wp + d] - Bx[H + wm2 + d]));
            lx = (Jy * bz - Jz * by) * 2500.0f;
            ly = (Jz * bx - Jx * bz) * 2500.0f;
            lz = (Jx * by - Jy * bx) * 2500.0f;
            char* xr = smc + O_X + r * XSTRIDE;
            *(uint32_t*)(xr)      = packh(Fb[s], Fb[SP + s]);
            *(uint32_t*)(xr + 4)  = packh(Fb[2 * SP + s], bx);
            *(uint32_t*)(xr + 8)  = packh(by, bz);
            *(uint32_t*)(xr + 12) = 0u;
            *(uint32_t*)(xr + 16) = 0u;
            *(uint32_t*)(xr + 20) = 0u;
            *(uint32_t*)(xr + 24) = 0u;
            *(uint32_t*)(xr + 28) = 0u;
        }
        __syncthreads();

        float c[4][4][4];

        // ---------------- L1: 16 -> 128 (1 k-step) ----------------
        {
            uint2 Bfr[4];
            #pragma unroll
            for (int t = 0; t < 4; t++)
                Bfr[t] = lds_u2(smb + O_W1T + ((wn * 4 + t) * 32 + lane) * 8);
            #pragma unroll
            for (int m = 0; m < 4; m++) {
                #pragma unroll
                for (int t = 0; t < 4; t++)
                    #pragma unroll
                    for (int q = 0; q < 4; q++) c[m][t][q] = 0.f;
                uint32_t a[4];
                LDSM4(a, abase + (uint32_t)((wm * 4 + m) * 16) * XSTRIDE);
                #pragma unroll
                for (int t = 0; t < 4; t++) MMA(c[m][t], a, Bfr[t]);
            }
        }
        __syncthreads();
        epilogue<4>(c, wn * 32, bias1, smc, wm, lane);
        __syncthreads();

        // ---------------- L2: 128 -> 128 (8 k-steps) ----------------
        #pragma unroll
        for (int m = 0; m < 4; m++)
            #pragma unroll
            for (int t = 0; t < 4; t++)
                #pragma unroll
                for (int q = 0; q < 4; q++) c[m][t][q] = 0.f;
        #pragma unroll
        for (int sx = 0; sx < 8; sx++) {
            uint2 Bfr[4];
            #pragma unroll
            for (int t = 0; t < 4; t++)
                Bfr[t] = lds_u2(smb + O_W2T + (((wn * 8 + sx) * 4 + t) * 32 + lane) * 8);
            #pragma unroll
            for (int m = 0; m < 4; m++) {
                uint32_t a[4];
                LDSM4(a, abase + (uint32_t)((wm * 4 + m) * 16) * XSTRIDE + sx * 32);
                #pragma unroll
                for (int t = 0; t < 4; t++) MMA(c[m][t], a, Bfr[t]);
            }
        }
        __syncthreads();
        epilogue<4>(c, wn * 32, bias2, smc, wm, lane);
        __syncthreads();

        // ---------------- L3: 128 -> 64 (8 k-steps, 2 n-tiles/warp) ----------------
        #pragma unroll
        for (int m = 0; m < 4; m++)
            #pragma unroll
            for (int t = 0; t < 2; t++)
                #pragma unroll
                for (int q = 0; q < 4; q++) c[m][t][q] = 0.f;
        #pragma unroll
        for (int sx = 0; sx < 8; sx++) {
            uint2 Bfr[2];
            #pragma unroll
            for (int t = 0; t < 2; t++)
                Bfr[t] = lds_u2(smb + O_W3T + (((wn * 8 + sx) * 2 + t) * 32 + lane) * 8);
            #pragma unroll
            for (int m = 0; m < 4; m++) {
                uint32_t a[4];
                LDSM4(a, abase + (uint32_t)((wm * 4 + m) * 16) * XSTRIDE + sx * 32);
                #pragma unroll
                for (int t = 0; t < 2; t++) MMA(c[m][t], a, Bfr[t]);
            }
        }
        __syncthreads();
        epilogue<2>(c, wn * 16, bias3, smc, wm, lane);
        __syncthreads();

        // ---------------- L4: 64 -> 3 scalar fp32 + lorentz + store ----------------
        if (tid < 128) {
            const float* W4s = (const float*)(smc + O_W4);
            const float* B4s = (const float*)(smc + O_B4);
            float e0 = B4s[0], e1 = B4s[1], e2 = B4s[2];
            #pragma unroll
            for (int j = 0; j < 8; j++) {
                uint4 q = *(const uint4*)(smc + O_X + r * XSTRIDE + (j << 4));
                const uint32_t ws[4] = {q.x, q.y, q.z, q.w};
                #pragma unroll
                for (int qd = 0; qd < 4; qd++) {
                    float2 f = __half22float2(*(const __half2*)&ws[qd]);
                    const int cc = j * 8 + qd * 2;
                    e0 += f.x * W4s[cc * 3]     + f.y * W4s[(cc + 1) * 3];
                    e1 += f.x * W4s[cc * 3 + 1] + f.y * W4s[(cc + 1) * 3 + 1];
                    e2 += f.x * W4s[cc * 3 + 2] + f.y * W4s[(cc + 1) * 3 + 2];
                }
            }
            float* ob = out + b * 3 * SP;
            ob[s]          = lx + 0.1f * e0;
            ob[SP + s]     = ly + 0.1f * e1;
            ob[2 * SP + s] = lz + 0.1f * e2;
        }
    }
}

extern "C" void kernel_launch(void* const* d_in, const int* in_sizes, int n_in,
                              void* d_out, int out_size)
{
    (void)in_sizes; (void)n_in; (void)out_size;
    cudaFuncSetAttribute(mhd_mma, cudaFuncAttributeMaxDynamicSharedMemorySize, SMEM_BYTES);
    mhd_mma<<<GRID, TB, SMEM_BYTES>>>(
        (const float*)d_in[0], (const float*)d_in[1], (const float*)d_in[2],
        (const float*)d_in[3], (const float*)d_in[4], (const float*)d_in[5],
        (const float*)d_in[6], (const float*)d_in[7], (const float*)d_in[8],
        (const float*)d_in[9], (float*)d_out);
}

// round 8
// speedup vs baseline: 19.9302x; 1.0751x over previous
#include <cuda_runtime.h>
#include <cuda_fp16.h>
#include <cstdint>

// lorentz (fp32 exact) + 0.1 * MLP via mma.sync m16n8k16 (f16 in, f32 accum).
// R8: ping-pong feature buffer, P0/L4 overlap, 6 barriers/tile, staging amortized x4.

#define SP    262144
#define TB    256
#define GRID  512
#define TILES 8          // 512*8*128 = 524288 voxels

// smem byte offsets
#define O_X    0         // [128 rows][136 halfs] = 34816 B (272 B stride)
#define O_F1   34816     // [128 rows][24 halfs]  = 6144 B (48 B stride)
#define O_F2   40960     // 6144
#define O_LZ1  47104     // 128*3 f32 = 1536
#define O_LZ2  48640     // 1536
#define O_W2T  50176     // 4096 frag entries * 8B = 32768
#define O_W3T  82944     // 2048 * 8 = 16384
#define O_W1T  99328     // 512 * 8 = 4096
#define O_B1   103424    // 128 f32
#define O_B2   103936
#define O_B3   104448    // 64 f32
#define O_W4   104704    // 192 f32
#define O_B4   105472    // 3 f32
#define SMEM_BYTES 105488
#define XSTRIDE 272
#define FSTRIDE 48

#define LDSM4(a, addr) asm volatile( \
    "ldmatrix.sync.aligned.m8n8.x4.shared.b16 {%0,%1,%2,%3}, [%4];" \
    : "=r"((a)[0]), "=r"((a)[1]), "=r"((a)[2]), "=r"((a)[3]) : "r"(addr))

#define MMA(c, a, b) asm volatile( \
    "mma.sync.aligned.m16n8k16.row.col.f32.f16.f16.f32 " \
    "{%0,%1,%2,%3}, {%4,%5,%6,%7}, {%8,%9}, {%0,%1,%2,%3};" \
    : "+f"((c)[0]), "+f"((c)[1]), "+f"((c)[2]), "+f"((c)[3]) \
    : "r"((a)[0]), "r"((a)[1]), "r"((a)[2]), "r"((a)[3]), "r"((b).x), "r"((b).y))

__device__ __forceinline__ uint32_t smem_u32(const void* p) {
    uint32_t a;
    asm("{ .reg .u64 t; cvta.to.shared.u64 t, %1; cvt.u32.u64 %0, t; }" : "=r"(a) : "l"(p));
    return a;
}
__device__ __forceinline__ uint2 lds_u2(uint32_t addr) {
    uint2 v;
    asm volatile("ld.shared.v2.b32 {%0,%1}, [%2];" : "=r"(v.x), "=r"(v.y) : "r"(addr));
    return v;
}
__device__ __forceinline__ uint32_t packh(float a, float b) {
    __half2 h = __floats2half2_rn(a, b);
    return *(uint32_t*)&h;
}
__device__ __forceinline__ uint32_t gelu_pack(float a, float b) {
    __half2 x = __floats2half2_rn(a, b);
    const __half2 c0 = __float2half2_rn(0.7978845608f);
    const __half2 c1 = __float2half2_rn(0.03567740814f);
    __half2 u = __hmul2(x, x);
    __half2 z = __hmul2(x, __hfma2(u, c1, c0));
    uint32_t zi = *(uint32_t*)&z, ti;
    asm("tanh.approx.f16x2 %0, %1;" : "=r"(ti) : "r"(zi));
    __half2 t = *(__half2*)&ti;
    __half2 hh = __hmul2(x, __float2half2_rn(0.5f));
    __half2 g = __hfma2(hh, t, hh);
    return *(uint32_t*)&g;
}

// epilogue: C frags -> +bias -> gelu -> f16 into X
template <int NT>
__device__ __forceinline__ void epilogue(float c[4][4][4], int nbase, const float* bias,
                                         char* smc, int wm, int lane) {
    const int rsub = lane >> 2;
    const int ncol = (lane & 3) * 2;
    #pragma unroll
    for (int m = 0; m < 4; m++) {
        const int row0 = (wm * 4 + m) * 16 + rsub;
        #pragma unroll
        for (int t = 0; t < NT; t++) {
            const int n = nbase + t * 8 + ncol;
            const float b0 = bias[n], b1 = bias[n + 1];
            uint32_t g01 = gelu_pack(c[m][t][0] + b0, c[m][t][1] + b1);
            uint32_t g23 = gelu_pack(c[m][t][2] + b0, c[m][t][3] + b1);
            *(uint32_t*)(smc + O_X + row0 * XSTRIDE + n * 2) = g01;
            *(uint32_t*)(smc + O_X + (row0 + 8) * XSTRIDE + n * 2) = g23;
        }
    }
}

// P0: features -> F[fo] (cols 0-5), lorentz -> LZ[lzo]. r in [0,128).
__device__ __forceinline__ void p0_phase(const float* __restrict__ flow,
                                         const float* __restrict__ Bf,
                                         char* smc, int fo, int lzo, int tile, int r) {
    const int v = tile * 128 + r;
    const int b = v >> 18;
    const int s = v & (SP - 1);
    const int h = s >> 12, w = (s >> 6) & 63, d = s & 63;
    const float* Fb = flow + b * 3 * SP;
    const float* Bx = Bf + b * 3 * SP;
    const float* By = Bx + SP;
    const float* Bz = Bx + 2 * SP;
    const int H = h << 12, Wo = w << 6;
    const int hp = ((h + 1) & 63) << 12, hm = ((h - 1) & 63) << 12;
    const int wp = ((w + 1) & 63) << 6,  wm2 = ((w - 1) & 63) << 6;
    const int dp = (d + 1) & 63, dm = (d - 1) & 63;
    const float bx = Bx[H + Wo + d], by = By[H + Wo + d], bz = Bz[H + Wo + d];
    const float Jx = 0.5f * ((Bz[H + wp + d] - Bz[H + wm2 + d]) - (By[H + Wo + dp] - By[H + Wo + dm]));
    const float Jy = 0.5f * ((Bx[H + Wo + dp] - Bx[H + Wo + dm]) - (Bz[hp + Wo + d] - Bz[hm + Wo + d]));
    const float Jz = 0.5f * ((By[hp + Wo + d] - By[hm + Wo + d]) - (Bx[H + wp + d] - Bx[H + wm2 + d]));
    char* xr = smc + fo + r * FSTRIDE;
    *(uint32_t*)(xr)     = packh(Fb[s], Fb[SP + s]);
    *(uint32_t*)(xr + 4) = packh(Fb[2 * SP + s], bx);
    *(uint32_t*)(xr + 8) = packh(by, bz);
    float* lz = (float*)(smc + lzo) + r * 3;
    lz[0] = (Jy * bz - Jz * by) * 2500.0f;
    lz[1] = (Jz * bx - Jx * bz) * 2500.0f;
    lz[2] = (Jx * by - Jy * bx) * 2500.0f;
}

// L4: 64 -> 3 scalar fp32 + lorentz(from LZ) + store. r in [0,128).
__device__ __forceinline__ void l4_phase(char* smc, int lzo, int tile, int r,
                                         float* __restrict__ out) {
    const int v = tile * 128 + r;
    const int b = v >> 18;
    const int s = v & (SP - 1);
    const float* W4s = (const float*)(smc + O_W4);
    const float* B4s = (const float*)(smc + O_B4);
    float e0 = B4s[0], e1 = B4s[1], e2 = B4s[2];
    #pragma unroll
    for (int j = 0; j < 8; j++) {
        uint4 q = *(const uint4*)(smc + O_X + r * XSTRIDE + (j << 4));
        const uint32_t ws[4] = {q.x, q.y, q.z, q.w};
        #pragma unroll
        for (int qd = 0; qd < 4; qd++) {
            float2 f = __half22float2(*(const __half2*)&ws[qd]);
            const int cc = j * 8 + qd * 2;
            e0 += f.x * W4s[cc * 3]     + f.y * W4s[(cc + 1) * 3];
            e1 += f.x * W4s[cc * 3 + 1] + f.y * W4s[(cc + 1) * 3 + 1];
            e2 += f.x * W4s[cc * 3 + 2] + f.y * W4s[(cc + 1) * 3 + 2];
        }
    }
    const float* lz = (const float*)(smc + lzo) + r * 3;
    float* ob = out + b * 3 * SP;
    ob[s]          = lz[0] + 0.1f * e0;
    ob[SP + s]     = lz[1] + 0.1f * e1;
    ob[2 * SP + s] = lz[2] + 0.1f * e2;
}

__global__ void __launch_bounds__(TB, 2)
mhd_mma(const float* __restrict__ flow, const float* __restrict__ Bf,
        const float* __restrict__ W1, const float* __restrict__ b1,
        const float* __restrict__ W2, const float* __restrict__ b2,
        const float* __restrict__ W3, const float* __restrict__ b3,
        const float* __restrict__ W4, const float* __restrict__ b4,
        float* __restrict__ out)
{
    extern __shared__ char smc[];
    const int tid  = threadIdx.x;
    const int wid  = tid >> 5;
    const int lane = tid & 31;
    const int wm   = wid >> 2;      // 0..1 : M half
    const int wn   = wid & 3;       // 0..3 : N quarter
    const uint32_t smb = smem_u32(smc);

    // ---------------- stage weight fragment tables (once per CTA) ----------------
    for (int e = tid; e < 4096; e += TB) {      // W2 frags
        int l = e & 31, t = (e >> 5) & 3, s = (e >> 7) & 7, w = e >> 10;
        int n = w * 32 + t * 8 + (l >> 2);
        int k0 = s * 16 + (l & 3) * 2;
        uint2 v;
        v.x = packh(W2[k0 * 128 + n], W2[(k0 + 1) * 128 + n]);
        v.y = packh(W2[(k0 + 8) * 128 + n], W2[(k0 + 9) * 128 + n]);
        *(uint2*)(smc + O_W2T + e * 8) = v;
    }
    for (int e = tid; e < 2048; e += TB) {      // W3 frags
        int l = e & 31, t = (e >> 5) & 1, s = (e >> 6) & 7, w = e >> 9;
        int n = w * 16 + t * 8 + (l >> 2);
        int k0 = s * 16 + (l & 3) * 2;
        uint2 v;
        v.x = packh(W3[k0 * 64 + n], W3[(k0 + 1) * 64 + n]);
        v.y = packh(W3[(k0 + 8) * 64 + n], W3[(k0 + 9) * 64 + n]);
        *(uint2*)(smc + O_W3T + e * 8) = v;
    }
    for (int e = tid; e < 512; e += TB) {       // W1 frags (k>=6 zero)
        int l = e & 31, t = (e >> 5) & 3, w = e >> 7;
        int n = w * 32 + t * 8 + (l >> 2);
        int k0 = (l & 3) * 2;
        float f0 = (k0 < 6) ? W1[k0 * 128 + n] : 0.f;
        float f1 = (k0 + 1 < 6) ? W1[(k0 + 1) * 128 + n] : 0.f;
        uint2 v;
        v.x = packh(f0, f1);
        v.y = 0u;
        *(uint2*)(smc + O_W1T + e * 8) = v;
    }
    // zero F1+F2 (cols 6-15 must stay zero; P0 writes only cols 0-5)
    for (int i = tid; i < 3072; i += TB) *(uint32_t*)(smc + O_F1 + 4 * i) = 0u;
    for (int i = tid; i < 128; i += TB) ((float*)(smc + O_B1))[i] = b1[i];
    for (int i = tid; i < 128; i += TB) ((float*)(smc + O_B2))[i] = b2[i];
    for (int i = tid; i < 64;  i += TB) ((float*)(smc + O_B3))[i] = b3[i];
    for (int i = tid; i < 192; i += TB) ((float*)(smc + O_W4))[i] = W4[i];
    if (tid < 3) ((float*)(smc + O_B4))[tid] = b4[tid];
    __syncthreads();

    // prologue P0 for tile0 (warps 4-7)
    if (tid >= 128) p0_phase(flow, Bf, smc, O_F1, O_LZ1, blockIdx.x, tid - 128);
    __syncthreads();

    const float* bias1 = (const float*)(smc + O_B1);
    const float* bias2 = (const float*)(smc + O_B2);
    const float* bias3 = (const float*)(smc + O_B3);

    int foc = O_F1, fon = O_F2, lzc = O_LZ1, lzn = O_LZ2;

    for (int it = 0; it < TILES; it++) {
        const int tile = it * GRID + blockIdx.x;
        // ldmatrix base into F[cur]
        const uint32_t fbase = smb + (uint32_t)foc + (uint32_t)(lane & 15) * FSTRIDE
                             + ((lane >> 4) << 4);
        const uint32_t abase = smb + O_X + (uint32_t)(lane & 15) * XSTRIDE + ((lane >> 4) << 4);

        float c[4][4][4];

        // ---------------- L1: F[cur] (16 cols) -> X (128 cols). No internal barrier:
        // MMA reads F, epilogue writes X (disjoint; X free since last loop-end sync).
        {
            uint2 Bfr[4];
            #pragma unroll
            for (int t = 0; t < 4; t++)
                Bfr[t] = lds_u2(smb + O_W1T + ((wn * 4 + t) * 32 + lane) * 8);
            #pragma unroll
            for (int m = 0; m < 4; m++) {
                #pragma unroll
                for (int t = 0; t < 4; t++)
                    #pragma unroll
                    for (int q = 0; q < 4; q++) c[m][t][q] = 0.f;
                uint32_t a[4];
                LDSM4(a, fbase + (uint32_t)((wm * 4 + m) * 16) * FSTRIDE);
                #pragma unroll
                for (int t = 0; t < 4; t++) MMA(c[m][t], a, Bfr[t]);
            }
        }
        epilogue<4>(c, wn * 32, bias1, smc, wm, lane);
        __syncthreads();                                   // sync1: X(x1) complete

        // ---------------- L2: X -> X (in place, 8 k-steps) ----------------
        #pragma unroll
        for (int m = 0; m < 4; m++)
            #pragma unroll
            for (int t = 0; t < 4; t++)
                #pragma unroll
                for (int q = 0; q < 4; q++) c[m][t][q] = 0.f;
        #pragma unroll
        for (int sx = 0; sx < 8; sx++) {
            uint2 Bfr[4];
            #pragma unroll
            for (int t = 0; t < 4; t++)
                Bfr[t] = lds_u2(smb + O_W2T + (((wn * 8 + sx) * 4 + t) * 32 + lane) * 8);
            #pragma unroll
            for (int m = 0; m < 4; m++) {
                uint32_t a[4];
                LDSM4(a, abase + (uint32_t)((wm * 4 + m) * 16) * XSTRIDE + sx * 32);
                #pragma unroll
                for (int t = 0; t < 4; t++) MMA(c[m][t], a, Bfr[t]);
            }
        }
        __syncthreads();                                   // sync2: all reads of x1 done
        epilogue<4>(c, wn * 32, bias2, smc, wm, lane);
        __syncthreads();                                   // sync3: X(x2) complete

        // ---------------- L3: X -> X cols 0-63 (8 k-steps, 2 n-tiles/warp) ----------------
        #pragma unroll
        for (int m = 0; m < 4; m++)
            #pragma unroll
            for (int t = 0; t < 2; t++)
                #pragma unroll
                for (int q = 0; q < 4; q++) c[m][t][q] = 0.f;
        #pragma unroll
        for (int sx = 0; sx < 8; sx++) {
            uint2 Bfr[2];
            #pragma unroll
            for (int t = 0; t < 2; t++)
                Bfr[t] = lds_u2(smb + O_W3T + (((wn * 8 + sx) * 2 + t) * 32 + lane) * 8);
            #pragma unroll
            for (int m = 0; m < 4; m++) {
                uint32_t a[4];
                LDSM4(a, abase + (uint32_t)((wm * 4 + m) * 16) * XSTRIDE + sx * 32);
                #pragma unroll
                for (int t = 0; t < 2; t++) MMA(c[m][t], a, Bfr[t]);
            }
        }
        __syncthreads();                                   // sync4: all reads of x2 done
        epilogue<2>(c, wn * 16, bias3, smc, wm, lane);
        __syncthreads();                                   // sync5: X(x3) complete

        // ---------------- phase e: L4(t) on warps 0-3 || P0(t+1) on warps 4-7 ----------------
        if (tid < 128) {
            l4_phase(smc, lzc, tile, tid, out);
        } else if (it + 1 < TILES) {
            p0_phase(flow, Bf, smc, fon, lzn, tile + GRID, tid - 128);
        }
        __syncthreads();                                   // sync0 for next iteration

        int tmp = foc; foc = fon; fon = tmp;
        tmp = lzc; lzc = lzn; lzn = tmp;
    }
}

extern "C" void kernel_launch(void* const* d_in, const int* in_sizes, int n_in,
                              void* d_out, int out_size)
{
    (void)in_sizes; (void)n_in; (void)out_size;
    cudaFuncSetAttribute(mhd_mma, cudaFuncAttributeMaxDynamicSharedMemorySize, SMEM_BYTES);
    mhd_mma<<<GRID, TB, SMEM_BYTES>>>(
        (const float*)d_in[0], (const float*)d_in[1], (const float*)d_in[2],
        (const float*)d_in[3], (const float*)d_in[4], (const float*)d_in[5],
        (const float*)d_in[6], (const float*)d_in[7], (const float*)d_in[8],
        (const float*)d_in[9], (float*)d_out);
}

// round 9
// speedup vs baseline: 26.3086x; 1.3200x over previous
#include <cuda_runtime.h>
#include <cuda_fp16.h>
#include <cstdint>

// R9: warp-local MLP dataflow. Each warp owns 16 voxels, computes all features of
// every layer; gelu'd f16 C-fragments ARE the next layer's A-fragments (identical
// lane layout). Zero inter-layer barriers; SMEM holds only weight B-fragments.

#define SP    262144
#define TB    256
#define GRID  512
#define TILES 8          // 512*8*128 = 524288 voxels

// smem byte offsets (weights only, ~52 KB)
#define O_W2T  0         // 2048 entries * 16 B = 32768 (sx<8, tp<8, lane)
#define O_W3T  32768     // 1024 * 16 = 16384 (sx<8, tp<4, lane)
#define O_W1T  49152     // 256 * 8 = 2048 (tp<8, lane)
#define O_B1H  51200     // 64 * 4
#define O_B2H  51456     // 64 * 4
#define O_B3H  51712     // 32 * 4
#define O_W4H  51840     // 96 * 4  (c*32 + p)
#define O_B4   52224     // 3 f32
#define SMEM_BYTES 52240

// f16-accumulator MMAs
#define MMAH16(c0, c1, a0, a1, a2, a3, b0, b1) asm volatile( \
    "mma.sync.aligned.m16n8k16.row.col.f16.f16.f16.f16 " \
    "{%0,%1}, {%2,%3,%4,%5}, {%6,%7}, {%0,%1};" \
    : "+r"(c0), "+r"(c1) \
    : "r"(a0), "r"(a1), "r"(a2), "r"(a3), "r"(b0), "r"(b1))

#define MMAH8(c0, c1, a0, a1, b0) asm volatile( \
    "mma.sync.aligned.m16n8k8.row.col.f16.f16.f16.f16 " \
    "{%0,%1}, {%2,%3}, {%4}, {%0,%1};" \
    : "+r"(c0), "+r"(c1) : "r"(a0), "r"(a1), "r"(b0))

__device__ __forceinline__ uint32_t smem_u32(const void* p) {
    uint32_t a;
    asm("{ .reg .u64 t; cvta.to.shared.u64 t, %1; cvt.u32.u64 %0, t; }" : "=r"(a) : "l"(p));
    return a;
}
__device__ __forceinline__ uint32_t lds32(uint32_t a) {
    uint32_t v; asm volatile("ld.shared.b32 %0, [%1];" : "=r"(v) : "r"(a)); return v;
}
__device__ __forceinline__ uint2 lds64(uint32_t a) {
    uint2 v; asm volatile("ld.shared.v2.b32 {%0,%1}, [%2];" : "=r"(v.x), "=r"(v.y) : "r"(a)); return v;
}
__device__ __forceinline__ uint4 lds128(uint32_t a) {
    uint4 v;
    asm volatile("ld.shared.v4.b32 {%0,%1,%2,%3}, [%4];"
                 : "=r"(v.x), "=r"(v.y), "=r"(v.z), "=r"(v.w) : "r"(a));
    return v;
}
__device__ __forceinline__ uint32_t packh(float a, float b) {
    __half2 h = __floats2half2_rn(a, b);
    return *(uint32_t*)&h;
}
// bias-add + gelu(tanh) on packed f16x2
__device__ __forceinline__ uint32_t gb(uint32_t cu, uint32_t bu) {
    __half2 x = __hadd2(*(__half2*)&cu, *(__half2*)&bu);
    const __half2 c0 = __float2half2_rn(0.7978845608f);
    const __half2 c1 = __float2half2_rn(0.03567740814f);
    __half2 u = __hmul2(x, x);
    __half2 z = __hmul2(x, __hfma2(u, c1, c0));
    uint32_t zi = *(uint32_t*)&z, ti;
    asm("tanh.approx.f16x2 %0, %1;" : "=r"(ti) : "r"(zi));
    __half2 t = *(__half2*)&ti;
    __half2 hh = __hmul2(x, __float2half2_rn(0.5f));
    __half2 g = __hfma2(hh, t, hh);
    return *(uint32_t*)&g;
}

__global__ void __launch_bounds__(TB, 2)
mhd_wl(const float* __restrict__ flow, const float* __restrict__ Bf,
       const float* __restrict__ W1, const float* __restrict__ b1,
       const float* __restrict__ W2, const float* __restrict__ b2,
       const float* __restrict__ W3, const float* __restrict__ b3,
       const float* __restrict__ W4, const float* __restrict__ b4,
       float* __restrict__ out)
{
    extern __shared__ char smc[];
    const int tid  = threadIdx.x;
    const int wid  = tid >> 5;
    const int lane = tid & 31;
    const int q    = lane & 3;       // k/col pair selector
    const int rsub = lane >> 2;      // row within 8
    const uint32_t smb = smem_u32(smc);

    // ---------------- stage weight B-fragment tables (once per CTA) ----------------
    // W2T: entry e = (sx*8+tp)*32+lane, 16B = frags for t=2tp, 2tp+1
    for (int e = tid; e < 2048; e += TB) {
        int l = e & 31, tp = (e >> 5) & 7, sx = e >> 8;
        int n0 = (2 * tp) * 8 + (l >> 2), n1 = n0 + 8;
        int k0 = sx * 16 + (l & 3) * 2;
        uint4 v;
        v.x = packh(W2[k0 * 128 + n0],       W2[(k0 + 1) * 128 + n0]);
        v.y = packh(W2[(k0 + 8) * 128 + n0], W2[(k0 + 9) * 128 + n0]);
        v.z = packh(W2[k0 * 128 + n1],       W2[(k0 + 1) * 128 + n1]);
        v.w = packh(W2[(k0 + 8) * 128 + n1], W2[(k0 + 9) * 128 + n1]);
        *(uint4*)(smc + O_W2T + e * 16) = v;
    }
    // W3T: e = (sx*4+tp)*32+lane
    for (int e = tid; e < 1024; e += TB) {
        int l = e & 31, tp = (e >> 5) & 3, sx = e >> 7;
        int n0 = (2 * tp) * 8 + (l >> 2), n1 = n0 + 8;
        int k0 = sx * 16 + (l & 3) * 2;
        uint4 v;
        v.x = packh(W3[k0 * 64 + n0],       W3[(k0 + 1) * 64 + n0]);
        v.y = packh(W3[(k0 + 8) * 64 + n0], W3[(k0 + 9) * 64 + n0]);
        v.z = packh(W3[k0 * 64 + n1],       W3[(k0 + 1) * 64 + n1]);
        v.w = packh(W3[(k0 + 8) * 64 + n1], W3[(k0 + 9) * 64 + n1]);
        *(uint4*)(smc + O_W3T + e * 16) = v;
    }
    // W1T: e = tp*32+lane, 8B = k8 frags for t=2tp, 2tp+1 (k rows >=6 zero)
    for (int e = tid; e < 256; e += TB) {
        int l = e & 31, tp = e >> 5;
        int n0 = (2 * tp) * 8 + (l >> 2), n1 = n0 + 8;
        int k0 = (l & 3) * 2;
        float a0 = (k0 < 6) ? W1[k0 * 128 + n0] : 0.f;
        float a1 = (k0 + 1 < 6) ? W1[(k0 + 1) * 128 + n0] : 0.f;
        float a2 = (k0 < 6) ? W1[k0 * 128 + n1] : 0.f;
        float a3 = (k0 + 1 < 6) ? W1[(k0 + 1) * 128 + n1] : 0.f;
        uint2 v; v.x = packh(a0, a1); v.y = packh(a2, a3);
        *(uint2*)(smc + O_W1T + e * 8) = v;
    }
    // bias tables: entry (t*4+q) -> features {8t+2q, +1}
    for (int i = tid; i < 64; i += TB)
        *(uint32_t*)(smc + O_B1H + i * 4) = packh(b1[(i >> 2) * 8 + (i & 3) * 2],
                                                  b1[(i >> 2) * 8 + (i & 3) * 2 + 1]);
    for (int i = tid; i < 64; i += TB)
        *(uint32_t*)(smc + O_B2H + i * 4) = packh(b2[(i >> 2) * 8 + (i & 3) * 2],
                                                  b2[(i >> 2) * 8 + (i & 3) * 2 + 1]);
    for (int i = tid; i < 32; i += TB)
        *(uint32_t*)(smc + O_B3H + i * 4) = packh(b3[(i >> 2) * 8 + (i & 3) * 2],
                                                  b3[(i >> 2) * 8 + (i & 3) * 2 + 1]);
    // W4H[c*32 + p] = {W4[2p][c], W4[2p+1][c]}
    for (int i = tid; i < 96; i += TB) {
        int c = i >> 5, p = i & 31;
        *(uint32_t*)(smc + O_W4H + i * 4) = packh(W4[2 * p * 3 + c], W4[(2 * p + 1) * 3 + c]);
    }
    if (tid < 3) ((float*)(smc + O_B4))[tid] = b4[tid];
    __syncthreads();   // only barrier in the kernel

    for (int it = 0; it < TILES; it++) {
        const int tile = it * GRID + blockIdx.x;
        const int vbase = tile * 128 + wid * 16;   // warp's 16-voxel strip
        const int b  = vbase >> 18;
        const int sb = vbase & (SP - 1);           // strip is contiguous in s
        const float* Fb = flow + b * 3 * SP;
        const float* Bx = Bf + b * 3 * SP;
        const float* By = Bx + SP;
        const float* Bz = Bx + 2 * SP;

        // ---------------- P0: features into A-frag regs + lorentz (lanes 0-15) ----
        const int s0 = sb + rsub, s1 = s0 + 8;     // this lane's two voxel rows
        uint32_t fa0, fa1;
        {
            float l0, h0, l1, h1;
            if (q == 0)      { l0 = Fb[s0]; h0 = Fb[SP + s0]; l1 = Fb[s1]; h1 = Fb[SP + s1]; }
            else if (q == 1) { l0 = Fb[2 * SP + s0]; h0 = Bx[s0]; l1 = Fb[2 * SP + s1]; h1 = Bx[s1]; }
            else if (q == 2) { l0 = By[s0]; h0 = Bz[s0]; l1 = By[s1]; h1 = Bz[s1]; }
            else             { l0 = h0 = l1 = h1 = 0.f; }
            fa0 = packh(l0, h0);
            fa1 = packh(l1, h1);
        }
        float lxv = 0.f, lyv = 0.f, lzv = 0.f;
        if (lane < 16) {
            const int sm = sb + lane;
            const int h = sm >> 12, w = (sm >> 6) & 63, d = sm & 63;
            const int H = h << 12, Wo = w << 6;
            const int hp = ((h + 1) & 63) << 12, hm = ((h - 1) & 63) << 12;
            const int wp = ((w + 1) & 63) << 6,  wm2 = ((w - 1) & 63) << 6;
            const int dp = (d + 1) & 63, dm = (d - 1) & 63;
            const float bx = Bx[H + Wo + d], by = By[H + Wo + d], bz = Bz[H + Wo + d];
            const float Jx = 0.5f * ((Bz[H + wp + d] - Bz[H + wm2 + d]) - (By[H + Wo + dp] - By[H + Wo + dm]));
            const float Jy = 0.5f * ((Bx[H + Wo + dp] - Bx[H + Wo + dm]) - (Bz[hp + Wo + d] - Bz[hm + Wo + d]));
            const float Jz = 0.5f * ((By[hp + Wo + d] - By[hm + Wo + d]) - (Bx[H + wp + d] - Bx[H + wm2 + d]));
            lxv = (Jy * bz - Jz * by) * 2500.0f;
            lyv = (Jz * bx - Jx * bz) * 2500.0f;
            lzv = (Jx * by - Jy * bx) * 2500.0f;
        }

        uint32_t a[16][2];    // activations (A-frags / gelu'd C-frags)
        uint32_t c[16][2];    // accumulators

        // ---------------- L1: 6(->8) -> 128, k8 MMA ----------------
        #pragma unroll
        for (int t = 0; t < 16; t++) { c[t][0] = 0u; c[t][1] = 0u; }
        #pragma unroll
        for (int tp = 0; tp < 8; tp++) {
            uint2 B1f = lds64(smb + O_W1T + (uint32_t)(tp * 32 + lane) * 8);
            MMAH8(c[2 * tp][0], c[2 * tp][1], fa0, fa1, B1f.x);
            MMAH8(c[2 * tp + 1][0], c[2 * tp + 1][1], fa0, fa1, B1f.y);
        }
        #pragma unroll
        for (int t = 0; t < 16; t++) {
            uint32_t bb = lds32(smb + O_B1H + (uint32_t)(t * 4 + q) * 4);
            a[t][0] = gb(c[t][0], bb);
            a[t][1] = gb(c[t][1], bb);
        }

        // ---------------- L2: 128 -> 128 ----------------
        #pragma unroll
        for (int t = 0; t < 16; t++) { c[t][0] = 0u; c[t][1] = 0u; }
        #pragma unroll
        for (int sx = 0; sx < 8; sx++) {
            const uint32_t a0 = a[2 * sx][0], a1 = a[2 * sx][1];
            const uint32_t a2 = a[2 * sx + 1][0], a3 = a[2 * sx + 1][1];
            #pragma unroll
            for (int tp = 0; tp < 8; tp++) {
                uint4 Bf2 = lds128(smb + O_W2T + (uint32_t)((sx * 8 + tp) * 32 + lane) * 16);
                MMAH16(c[2 * tp][0], c[2 * tp][1], a0, a1, a2, a3, Bf2.x, Bf2.y);
                MMAH16(c[2 * tp + 1][0], c[2 * tp + 1][1], a0, a1, a2, a3, Bf2.z, Bf2.w);
            }
        }
        #pragma unroll
        for (int t = 0; t < 16; t++) {
            uint32_t bb = lds32(smb + O_B2H + (uint32_t)(t * 4 + q) * 4);
            a[t][0] = gb(c[t][0], bb);
            a[t][1] = gb(c[t][1], bb);
        }

        // ---------------- L3: 128 -> 64 ----------------
        uint32_t c3[8][2];
        #pragma unroll
        for (int t = 0; t < 8; t++) { c3[t][0] = 0u; c3[t][1] = 0u; }
        #pragma unroll
        for (int sx = 0; sx < 8; sx++) {
            const uint32_t a0 = a[2 * sx][0], a1 = a[2 * sx][1];
            const uint32_t a2 = a[2 * sx + 1][0], a3 = a[2 * sx + 1][1];
            #pragma unroll
            for (int tp = 0; tp < 4; tp++) {
                uint4 Bf3 = lds128(smb + O_W3T + (uint32_t)((sx * 4 + tp) * 32 + lane) * 16);
                MMAH16(c3[2 * tp][0], c3[2 * tp][1], a0, a1, a2, a3, Bf3.x, Bf3.y);
                MMAH16(c3[2 * tp + 1][0], c3[2 * tp + 1][1], a0, a1, a2, a3, Bf3.z, Bf3.w);
            }
        }
        #pragma unroll
        for (int t = 0; t < 8; t++) {
            uint32_t bb = lds32(smb + O_B3H + (uint32_t)(t * 4 + q) * 4);
            c3[t][0] = gb(c3[t][0], bb);    // x3 in place
            c3[t][1] = gb(c3[t][1], bb);
        }

        // ---------------- L4: 64 -> 3 (hfma2 dot + quad butterfly) ----------------
        __half2 acc[2][3];
        #pragma unroll
        for (int r = 0; r < 2; r++)
            #pragma unroll
            for (int cc = 0; cc < 3; cc++) acc[r][cc] = __float2half2_rn(0.f);
        #pragma unroll
        for (int t = 0; t < 8; t++) {
            #pragma unroll
            for (int cc = 0; cc < 3; cc++) {
                uint32_t wu = lds32(smb + O_W4H + (uint32_t)(cc * 32 + t * 4 + q) * 4);
                __half2 wh = *(__half2*)&wu;
                acc[0][cc] = __hfma2(*(__half2*)&c3[t][0], wh, acc[0][cc]);
                acc[1][cc] = __hfma2(*(__half2*)&c3[t][1], wh, acc[1][cc]);
            }
        }
        float pe[2][3];
        #pragma unroll
        for (int r = 0; r < 2; r++)
            #pragma unroll
            for (int cc = 0; cc < 3; cc++) {
                float2 f = __half22float2(acc[r][cc]);
                float v = f.x + f.y;
                v += __shfl_xor_sync(0xffffffffu, v, 1);
                v += __shfl_xor_sync(0xffffffffu, v, 2);
                pe[r][cc] = v + ((const float*)(smc + O_B4))[cc];
            }
        // gather lorentz for this lane's two voxel rows from lanes 0-15
        const float Lx0 = __shfl_sync(0xffffffffu, lxv, rsub);
        const float Ly0 = __shfl_sync(0xffffffffu, lyv, rsub);
        const float Lz0 = __shfl_sync(0xffffffffu, lzv, rsub);
        const float Lx1 = __shfl_sync(0xffffffffu, lxv, rsub + 8);
        const float Ly1 = __shfl_sync(0xffffffffu, lyv, rsub + 8);
        const float Lz1 = __shfl_sync(0xffffffffu, lzv, rsub + 8);
        if (q < 3) {
            const float L0 = (q == 0) ? Lx0 : (q == 1) ? Ly0 : Lz0;
            const float L1 = (q == 0) ? Lx1 : (q == 1) ? Ly1 : Lz1;
            float* ob = out + b * 3 * SP + q * SP;
            ob[s0] = L0 + 0.1f * pe[0][q];
            ob[s1] = L1 + 0.1f * pe[1][q];
        }
    }
}

extern "C" void kernel_launch(void* const* d_in, const int* in_sizes, int n_in,
                              void* d_out, int out_size)
{
    (void)in_sizes; (void)n_in; (void)out_size;
    cudaFuncSetAttribute(mhd_wl, cudaFuncAttributeMaxDynamicSharedMemorySize, SMEM_BYTES);
    mhd_wl<<<GRID, TB, SMEM_BYTES>>>(
        (const float*)d_in[0], (const float*)d_in[1], (const float*)d_in[2],
        (const float*)d_in[3], (const float*)d_in[4], (const float*)d_in[5],
        (const float*)d_in[6], (const float*)d_in[7], (const float*)d_in[8],
        (const float*)d_in[9], (float*)d_out);
}